// round 3
// baseline (speedup 1.0000x reference)
#include <cuda_runtime.h>
#include <cuda_bf16.h>
#include <math_constants.h>
#include <cstdint>

#define NN 50000
#define NM_PAD 50048          // 391 * 128
#define NE 800000
#define DIM 256
#define NINNER 768
#define CAP 128

#define BM 128
#define BN 128
#define BK 32
#define KTOT 768              // effective K: [Xhi(256)|Xlo(256)|Xhi(256 again)]
#define NKT (KTOT / BK)       // 24
#define LDA 40                // As row stride (elements), 80B: conflict-free ldmatrix
#define LDB 136               // Bs row stride (elements), 272B

// ---------------- device scratch ----------------
__device__ float g_bias[NINNER];
__device__ float g_Y[(size_t)NN * NINNER];            // qkv fp32 [q|k|v]
__device__ int   g_cnt[NN];
__device__ int   g_adj[(size_t)NN * CAP];
__device__ __nv_bfloat16 g_A2[(size_t)NM_PAD * 512];  // [m][0:256)=Xhi, [256:512)=Xlo
__device__ __nv_bfloat16 g_B2[(size_t)KTOT * NINNER]; // rows 0-255 Whi, 256-511 Whi, 512-767 Wlo

// ---------------- helpers ----------------
__device__ __forceinline__ uint32_t smem_u32(const void* p) {
    uint32_t a;
    asm("{ .reg .u64 t; cvta.to.shared.u64 t, %1; cvt.u32.u64 %0, t; }" : "=r"(a) : "l"(p));
    return a;
}
__device__ __forceinline__ void cp16(uint32_t sdst, const void* gsrc) {
    asm volatile("cp.async.cg.shared.global [%0], [%1], 16;" :: "r"(sdst), "l"(gsrc));
}
__device__ __forceinline__ void cp_commit() { asm volatile("cp.async.commit_group;"); }
template<int N> __device__ __forceinline__ void cp_wait() {
    asm volatile("cp.async.wait_group %0;" :: "n"(N));
}
__device__ __forceinline__ void ldm_x4(uint32_t* r, uint32_t addr) {
    asm volatile("ldmatrix.sync.aligned.m8n8.x4.shared.b16 {%0,%1,%2,%3}, [%4];"
        : "=r"(r[0]), "=r"(r[1]), "=r"(r[2]), "=r"(r[3]) : "r"(addr));
}
__device__ __forceinline__ void ldm_x4t(uint32_t* r, uint32_t addr) {
    asm volatile("ldmatrix.sync.aligned.m8n8.x4.trans.shared.b16 {%0,%1,%2,%3}, [%4];"
        : "=r"(r[0]), "=r"(r[1]), "=r"(r[2]), "=r"(r[3]) : "r"(addr));
}
__device__ __forceinline__ void mma_bf16(float* d, const uint32_t* a, const uint32_t* b) {
    asm volatile(
        "mma.sync.aligned.m16n8k16.row.col.f32.bf16.bf16.f32 "
        "{%0,%1,%2,%3}, {%4,%5,%6,%7}, {%8,%9}, {%0,%1,%2,%3};"
        : "+f"(d[0]), "+f"(d[1]), "+f"(d[2]), "+f"(d[3])
        : "r"(a[0]), "r"(a[1]), "r"(a[2]), "r"(a[3]), "r"(b[0]), "r"(b[1]));
}

// ---------------- kernel 1: X -> split bf16 A2 ----------------
__global__ __launch_bounds__(256) void convertA_kernel(const float* __restrict__ X) {
    size_t t = (size_t)blockIdx.x * blockDim.x + threadIdx.x;
    if (t >= (size_t)NM_PAD * 32) return;
    int u = (int)(t & 31);
    int m = (int)(t >> 5);
    __nv_bfloat16 hi[8], lo[8];
    if (m < NN) {
        const float* src = X + (size_t)m * DIM + u * 8;
        float4 v0 = *reinterpret_cast<const float4*>(src);
        float4 v1 = *reinterpret_cast<const float4*>(src + 4);
        float vals[8] = {v0.x, v0.y, v0.z, v0.w, v1.x, v1.y, v1.z, v1.w};
#pragma unroll
        for (int j = 0; j < 8; j++) {
            hi[j] = __float2bfloat16(vals[j]);
            lo[j] = __float2bfloat16(vals[j] - __bfloat162float(hi[j]));
        }
    } else {
#pragma unroll
        for (int j = 0; j < 8; j++) { hi[j] = __float2bfloat16(0.f); lo[j] = __float2bfloat16(0.f); }
    }
    __nv_bfloat16* base = g_A2 + (size_t)m * 512;
    *reinterpret_cast<uint4*>(base + u * 8)       = *reinterpret_cast<uint4*>(hi);
    *reinterpret_cast<uint4*>(base + 256 + u * 8) = *reinterpret_cast<uint4*>(lo);
}

// ---------------- kernel 2: W -> split bf16 B2 + bias ----------------
__global__ __launch_bounds__(256) void packB_kernel(const float* __restrict__ Wq, const float* __restrict__ bq,
                                                    const float* __restrict__ Wk, const float* __restrict__ bk,
                                                    const float* __restrict__ Wv, const float* __restrict__ bv) {
    int t = blockIdx.x * blockDim.x + threadIdx.x;
    if (t < NINNER)
        g_bias[t] = (t < 256) ? bq[t] : (t < 512) ? bk[t - 256] : bv[t - 512];
    if (t >= KTOT * NINNER) return;
    int n = t % NINNER;
    int kc = t / NINNER;
    int k = (kc < 256) ? kc : (kc < 512) ? kc - 256 : kc - 512;
    bool want_lo = (kc >= 512);
    float w = (n < 256) ? Wq[k * 256 + n] : (n < 512) ? Wk[k * 256 + (n - 256)] : Wv[k * 256 + (n - 512)];
    __nv_bfloat16 h = __float2bfloat16(w);
    g_B2[(size_t)kc * NINNER + n] = want_lo ? __float2bfloat16(w - __bfloat162float(h)) : h;
}

// ---------------- kernel 3: bf16 HMMA GEMM: g_Y = A2 @ B2 + bias ----------------
__global__ __launch_bounds__(256) void gemm_mma_kernel() {
    __shared__ __nv_bfloat16 As[2][BM][LDA];
    __shared__ __nv_bfloat16 Bs[2][BK][LDB];

    const int tid = threadIdx.x;
    const int wid = tid >> 5;
    const int lane = tid & 31;
    const int wm = wid & 3;           // M warp (0..3) -> 32 rows each
    const int wn = wid >> 2;          // N warp (0..1) -> 64 cols each
    const int m0 = blockIdx.x * BM;
    const int n0 = blockIdx.y * BN;

    float acc[2][8][4];
#pragma unroll
    for (int i = 0; i < 2; i++)
#pragma unroll
        for (int j = 0; j < 8; j++)
#pragma unroll
            for (int q = 0; q < 4; q++) acc[i][j][q] = 0.f;

    auto load_stage = [&](int st, int kt) {
        int kc = kt * BK;
        int keff = (kc < 512) ? kc : kc - 512;
#pragma unroll
        for (int i = 0; i < 2; i++) {
            int idx = tid + i * 256;
            int r = idx >> 2, kq = idx & 3;
            cp16(smem_u32(&As[st][r][kq * 8]),
                 g_A2 + (size_t)(m0 + r) * 512 + keff + kq * 8);
        }
#pragma unroll
        for (int i = 0; i < 2; i++) {
            int idx = tid + i * 256;
            int r = idx >> 4, cq = idx & 15;
            cp16(smem_u32(&Bs[st][r][cq * 8]),
                 g_B2 + (size_t)(kc + r) * NINNER + n0 + cq * 8);
        }
        cp_commit();
    };

    load_stage(0, 0);

    for (int kt = 0; kt < NKT; kt++) {
        int st = kt & 1;
        if (kt + 1 < NKT) {
            load_stage(st ^ 1, kt + 1);
            cp_wait<1>();
        } else {
            cp_wait<0>();
        }
        __syncthreads();

#pragma unroll
        for (int kk = 0; kk < BK; kk += 16) {
            uint32_t a[2][4], b[4][4];
#pragma unroll
            for (int mi = 0; mi < 2; mi++) {
                int ar = wm * 32 + mi * 16 + (lane & 15);
                int ac = kk + ((lane >> 4) << 3);
                ldm_x4(a[mi], smem_u32(&As[st][ar][ac]));
            }
#pragma unroll
            for (int nt = 0; nt < 4; nt++) {
                int br = kk + (lane & 15);
                int bc = wn * 64 + nt * 16 + ((lane >> 4) << 3);
                ldm_x4t(b[nt], smem_u32(&Bs[st][br][bc]));
            }
#pragma unroll
            for (int mi = 0; mi < 2; mi++)
#pragma unroll
                for (int nj = 0; nj < 8; nj++)
                    mma_bf16(acc[mi][nj], a[mi], &b[nj >> 1][(nj & 1) * 2]);
        }
        __syncthreads();
    }

    // epilogue: add bias, store fp32
#pragma unroll
    for (int mi = 0; mi < 2; mi++) {
        int row0 = m0 + wm * 32 + mi * 16 + (lane >> 2);
#pragma unroll
        for (int nj = 0; nj < 8; nj++) {
            int nc = n0 + wn * 64 + nj * 8 + (lane & 3) * 2;
            float b0 = g_bias[nc], b1 = g_bias[nc + 1];
            if (row0 < NN) {
                float2 v = make_float2(acc[mi][nj][0] + b0, acc[mi][nj][1] + b1);
                *reinterpret_cast<float2*>(g_Y + (size_t)row0 * NINNER + nc) = v;
            }
            if (row0 + 8 < NN) {
                float2 v = make_float2(acc[mi][nj][2] + b0, acc[mi][nj][3] + b1);
                *reinterpret_cast<float2*>(g_Y + (size_t)(row0 + 8) * NINNER + nc) = v;
            }
        }
    }
}

// ---------------- kernel 4: zero counters ----------------
__global__ void zero_cnt_kernel() {
    int i = blockIdx.x * blockDim.x + threadIdx.x;
    if (i < NN) g_cnt[i] = 0;
}

// ---------------- kernel 5: scatter edges ----------------
__global__ void scatter_kernel(const int* __restrict__ src, const int* __restrict__ dst) {
    int e = blockIdx.x * blockDim.x + threadIdx.x;
    if (e < NE) {
        int d = dst[e];
        int p = atomicAdd(&g_cnt[d], 1);
        if (p < CAP) g_adj[(size_t)d * CAP + p] = src[e];
    }
}

// ---------------- kernel 6: per-dst online-softmax attention ----------------
__global__ __launch_bounds__(256) void attn_kernel(float* __restrict__ out) {
    const int d = blockIdx.x;
    const int h = threadIdx.x >> 5;
    const int lane = threadIdx.x & 31;

    int cnt = g_cnt[d];
    if (cnt > CAP) cnt = CAP;
    const int* adj = &g_adj[(size_t)d * CAP];

    const float kd = g_Y[(size_t)d * NINNER + 256 + h * 32 + lane];

    float m = -CUDART_INF_F;
    float z = 0.f;
    float acc = 0.f;
    const float scale = 0.17677669529663687f;  // 1/sqrt(32)

    for (int i = 0; i < cnt; i++) {
        int s = adj[i];
        const float* row = g_Y + (size_t)s * NINNER + h * 32 + lane;
        float qd = row[0];
        float dot = qd * kd;
#pragma unroll
        for (int off = 16; off > 0; off >>= 1)
            dot += __shfl_xor_sync(0xFFFFFFFFu, dot, off);
        float score = dot * scale;

        float mn = fmaxf(m, score);
        float corr = __expf(m - mn);
        float w = __expf(score - mn);
        float vd = row[512];
        z = z * corr + w;
        acc = acc * corr + w * vd;
        m = mn;
    }

    float r = (cnt > 0) ? acc / z : 0.f;
    out[(size_t)d * 256 + h * 32 + lane] = r;
}

// ---------------- launch ----------------
extern "C" void kernel_launch(void* const* d_in, const int* in_sizes, int n_in,
                              void* d_out, int out_size) {
    const float* x  = (const float*)d_in[0];
    const float* Wq = (const float*)d_in[1];
    const float* bq = (const float*)d_in[2];
    const float* Wk = (const float*)d_in[3];
    const float* bk = (const float*)d_in[4];
    const float* Wv = (const float*)d_in[5];
    const float* bv = (const float*)d_in[6];
    const int* src  = (const int*)d_in[7];
    const int* dst  = (const int*)d_in[8];
    float* out = (float*)d_out;

    size_t nconv = (size_t)NM_PAD * 32;
    convertA_kernel<<<(unsigned)((nconv + 255) / 256), 256>>>(x);
    packB_kernel<<<(KTOT * NINNER + 255) / 256, 256>>>(Wq, bq, Wk, bk, Wv, bv);

    dim3 ggrid(NM_PAD / BM, NINNER / BN);  // 391 x 6
    gemm_mma_kernel<<<ggrid, 256>>>();

    zero_cnt_kernel<<<(NN + 255) / 256, 256>>>();
    scatter_kernel<<<(NE + 255) / 256, 256>>>(src, dst);

    attn_kernel<<<NN, 256>>>(out);
}

// round 4
// speedup vs baseline: 2.0573x; 2.0573x over previous
#include <cuda_runtime.h>
#include <cuda_bf16.h>
#include <math_constants.h>
#include <cstdint>

#define NN 50000
#define NM_PAD 50048          // 391 * 128
#define NE 800000
#define DIM 256
#define NINNER 768
#define CAP 128

#define BM 128
#define BN 128
#define BK 32
#define KTOT 768              // effective K: [Xhi(256)|Xlo(256)|Xhi(256 again)]
#define NKT (KTOT / BK)       // 24
#define LDA 40                // As row stride (elements)
#define LDB 136               // Bs row stride (elements)

// ---------------- device scratch ----------------
__device__ float g_bias[NINNER];
__device__ float g_Y[(size_t)NN * NINNER];            // qkv fp32 [q|k|v]
__device__ int   g_cnt[NN];
__device__ int   g_adj[(size_t)NN * CAP];
__device__ __nv_bfloat16 g_A2[(size_t)NM_PAD * 512];  // [m][0:256)=Xhi, [256:512)=Xlo
__device__ __nv_bfloat16 g_B2[(size_t)KTOT * NINNER]; // rows 0-255 Whi, 256-511 Whi, 512-767 Wlo

// ---------------- helpers ----------------
__device__ __forceinline__ uint32_t smem_u32(const void* p) {
    uint32_t a;
    asm("{ .reg .u64 t; cvta.to.shared.u64 t, %1; cvt.u32.u64 %0, t; }" : "=r"(a) : "l"(p));
    return a;
}
__device__ __forceinline__ void cp16(uint32_t sdst, const void* gsrc) {
    asm volatile("cp.async.cg.shared.global [%0], [%1], 16;" :: "r"(sdst), "l"(gsrc));
}
__device__ __forceinline__ void cp_commit() { asm volatile("cp.async.commit_group;"); }
template<int N> __device__ __forceinline__ void cp_wait() {
    asm volatile("cp.async.wait_group %0;" :: "n"(N));
}
__device__ __forceinline__ void ldm_x4(uint32_t* r, uint32_t addr) {
    asm volatile("ldmatrix.sync.aligned.m8n8.x4.shared.b16 {%0,%1,%2,%3}, [%4];"
        : "=r"(r[0]), "=r"(r[1]), "=r"(r[2]), "=r"(r[3]) : "r"(addr));
}
__device__ __forceinline__ void ldm_x4t(uint32_t* r, uint32_t addr) {
    asm volatile("ldmatrix.sync.aligned.m8n8.x4.trans.shared.b16 {%0,%1,%2,%3}, [%4];"
        : "=r"(r[0]), "=r"(r[1]), "=r"(r[2]), "=r"(r[3]) : "r"(addr));
}
__device__ __forceinline__ void mma_bf16(float* d, const uint32_t* a, const uint32_t* b) {
    asm volatile(
        "mma.sync.aligned.m16n8k16.row.col.f32.bf16.bf16.f32 "
        "{%0,%1,%2,%3}, {%4,%5,%6,%7}, {%8,%9}, {%0,%1,%2,%3};"
        : "+f"(d[0]), "+f"(d[1]), "+f"(d[2]), "+f"(d[3])
        : "r"(a[0]), "r"(a[1]), "r"(a[2]), "r"(a[3]), "r"(b[0]), "r"(b[1]));
}

// ---------------- kernel 1: X -> split bf16 A2 ----------------
__global__ __launch_bounds__(256) void convertA_kernel(const float* __restrict__ X) {
    size_t t = (size_t)blockIdx.x * blockDim.x + threadIdx.x;
    if (t >= (size_t)NM_PAD * 32) return;
    int u = (int)(t & 31);
    int m = (int)(t >> 5);
    __nv_bfloat16 hi[8], lo[8];
    if (m < NN) {
        const float* src = X + (size_t)m * DIM + u * 8;
        float4 v0 = *reinterpret_cast<const float4*>(src);
        float4 v1 = *reinterpret_cast<const float4*>(src + 4);
        float vals[8] = {v0.x, v0.y, v0.z, v0.w, v1.x, v1.y, v1.z, v1.w};
#pragma unroll
        for (int j = 0; j < 8; j++) {
            hi[j] = __float2bfloat16(vals[j]);
            lo[j] = __float2bfloat16(vals[j] - __bfloat162float(hi[j]));
        }
    } else {
#pragma unroll
        for (int j = 0; j < 8; j++) { hi[j] = __float2bfloat16(0.f); lo[j] = __float2bfloat16(0.f); }
    }
    __nv_bfloat16* base = g_A2 + (size_t)m * 512;
    *reinterpret_cast<uint4*>(base + u * 8)       = *reinterpret_cast<uint4*>(hi);
    *reinterpret_cast<uint4*>(base + 256 + u * 8) = *reinterpret_cast<uint4*>(lo);
}

// ---------------- kernel 2: W -> split bf16 B2 + bias ----------------
__global__ __launch_bounds__(256) void packB_kernel(const float* __restrict__ Wq, const float* __restrict__ bq,
                                                    const float* __restrict__ Wk, const float* __restrict__ bk,
                                                    const float* __restrict__ Wv, const float* __restrict__ bv) {
    int t = blockIdx.x * blockDim.x + threadIdx.x;
    if (t < NINNER)
        g_bias[t] = (t < 256) ? bq[t] : (t < 512) ? bk[t - 256] : bv[t - 512];
    if (t >= KTOT * NINNER) return;
    int n = t % NINNER;
    int kc = t / NINNER;
    int k = (kc < 256) ? kc : (kc < 512) ? kc - 256 : kc - 512;
    bool want_lo = (kc >= 512);
    float w = (n < 256) ? Wq[k * 256 + n] : (n < 512) ? Wk[k * 256 + (n - 256)] : Wv[k * 256 + (n - 512)];
    __nv_bfloat16 h = __float2bfloat16(w);
    g_B2[(size_t)kc * NINNER + n] = want_lo ? __float2bfloat16(w - __bfloat162float(h)) : h;
}

// ---------------- kernel 3: bf16 HMMA GEMM: g_Y = A2 @ B2 + bias ----------------
__global__ __launch_bounds__(256) void gemm_mma_kernel() {
    __shared__ __nv_bfloat16 As[2][BM][LDA];
    __shared__ __nv_bfloat16 Bs[2][BK][LDB];

    const int tid = threadIdx.x;
    const int wid = tid >> 5;
    const int lane = tid & 31;
    const int wm = wid & 3;
    const int wn = wid >> 2;
    const int m0 = blockIdx.x * BM;
    const int n0 = blockIdx.y * BN;

    float acc[2][8][4];
#pragma unroll
    for (int i = 0; i < 2; i++)
#pragma unroll
        for (int j = 0; j < 8; j++)
#pragma unroll
            for (int q = 0; q < 4; q++) acc[i][j][q] = 0.f;

    auto load_stage = [&](int st, int kt) {
        int kc = kt * BK;
        int keff = (kc < 512) ? kc : kc - 512;
#pragma unroll
        for (int i = 0; i < 2; i++) {
            int idx = tid + i * 256;
            int r = idx >> 2, kq = idx & 3;
            cp16(smem_u32(&As[st][r][kq * 8]),
                 g_A2 + (size_t)(m0 + r) * 512 + keff + kq * 8);
        }
#pragma unroll
        for (int i = 0; i < 2; i++) {
            int idx = tid + i * 256;
            int r = idx >> 4, cq = idx & 15;
            cp16(smem_u32(&Bs[st][r][cq * 8]),
                 g_B2 + (size_t)(kc + r) * NINNER + n0 + cq * 8);
        }
        cp_commit();
    };

    load_stage(0, 0);

    for (int kt = 0; kt < NKT; kt++) {
        int st = kt & 1;
        if (kt + 1 < NKT) {
            load_stage(st ^ 1, kt + 1);
            cp_wait<1>();
        } else {
            cp_wait<0>();
        }
        __syncthreads();

#pragma unroll
        for (int kk = 0; kk < BK; kk += 16) {
            uint32_t a[2][4], b[4][4];
#pragma unroll
            for (int mi = 0; mi < 2; mi++) {
                int ar = wm * 32 + mi * 16 + (lane & 15);
                int ac = kk + ((lane >> 4) << 3);
                ldm_x4(a[mi], smem_u32(&As[st][ar][ac]));
            }
#pragma unroll
            for (int nt = 0; nt < 4; nt++) {
                int br = kk + (lane & 15);
                int bc = wn * 64 + nt * 16 + ((lane >> 4) << 3);
                ldm_x4t(b[nt], smem_u32(&Bs[st][br][bc]));
            }
#pragma unroll
            for (int mi = 0; mi < 2; mi++)
#pragma unroll
                for (int nj = 0; nj < 8; nj++)
                    mma_bf16(acc[mi][nj], a[mi], &b[nj >> 1][(nj & 1) * 2]);
        }
        __syncthreads();
    }

#pragma unroll
    for (int mi = 0; mi < 2; mi++) {
        int row0 = m0 + wm * 32 + mi * 16 + (lane >> 2);
#pragma unroll
        for (int nj = 0; nj < 8; nj++) {
            int nc = n0 + wn * 64 + nj * 8 + (lane & 3) * 2;
            float b0 = g_bias[nc], b1 = g_bias[nc + 1];
            if (row0 < NN) {
                float2 v = make_float2(acc[mi][nj][0] + b0, acc[mi][nj][1] + b1);
                *reinterpret_cast<float2*>(g_Y + (size_t)row0 * NINNER + nc) = v;
            }
            if (row0 + 8 < NN) {
                float2 v = make_float2(acc[mi][nj][2] + b0, acc[mi][nj][3] + b1);
                *reinterpret_cast<float2*>(g_Y + (size_t)(row0 + 8) * NINNER + nc) = v;
            }
        }
    }
}

// ---------------- kernel 4: zero counters ----------------
__global__ void zero_cnt_kernel() {
    int i = blockIdx.x * blockDim.x + threadIdx.x;
    if (i < NN) g_cnt[i] = 0;
}

// ---------------- kernel 5: scatter edges ----------------
__global__ void scatter_kernel(const int* __restrict__ src, const int* __restrict__ dst) {
    int e = blockIdx.x * blockDim.x + threadIdx.x;
    if (e < NE) {
        int d = dst[e];
        int p = atomicAdd(&g_cnt[d], 1);
        if (p < CAP) g_adj[(size_t)d * CAP + p] = src[e];
    }
}

// ---------------- kernel 6: warp-per-dst attention, all 8 heads per warp ----------------
// lane = h*4 + j; lane owns dims [lane*8, lane*8+8) of the 256-dim inner space.
__global__ __launch_bounds__(256) void attn_kernel(float* __restrict__ out) {
    const int d = blockIdx.x * 8 + (threadIdx.x >> 5);
    if (d >= NN) return;
    const int lane = threadIdx.x & 31;
    const int off = lane * 8;

    int cnt = g_cnt[d];
    if (cnt > CAP) cnt = CAP;
    const int* adj = &g_adj[(size_t)d * CAP];

    // cache this dst's K slice (8 floats)
    const float* krow = g_Y + (size_t)d * NINNER + 256 + off;
    float4 k0 = *reinterpret_cast<const float4*>(krow);
    float4 k1 = *reinterpret_cast<const float4*>(krow + 4);

    float m = -CUDART_INF_F;
    float z = 0.f;
    float4 a0 = make_float4(0.f, 0.f, 0.f, 0.f);
    float4 a1 = make_float4(0.f, 0.f, 0.f, 0.f);
    const float scale = 0.17677669529663687f;  // 1/sqrt(32)

    for (int i = 0; i < cnt; i++) {
        int s = adj[i];
        const float* row = g_Y + (size_t)s * NINNER + off;
        float4 q0 = *reinterpret_cast<const float4*>(row);
        float4 q1 = *reinterpret_cast<const float4*>(row + 4);
        float4 v0 = *reinterpret_cast<const float4*>(row + 512);
        float4 v1 = *reinterpret_cast<const float4*>(row + 512 + 4);

        float dot = q0.x * k0.x + q0.y * k0.y + q0.z * k0.z + q0.w * k0.w
                  + q1.x * k1.x + q1.y * k1.y + q1.z * k1.z + q1.w * k1.w;
        // reduce across the 4 lanes of this head
        dot += __shfl_xor_sync(0xFFFFFFFFu, dot, 1);
        dot += __shfl_xor_sync(0xFFFFFFFFu, dot, 2);
        float score = dot * scale;

        float mn = fmaxf(m, score);
        float corr = __expf(m - mn);      // 0 on first edge (m = -inf)
        float w = __expf(score - mn);
        z = z * corr + w;
        a0.x = a0.x * corr + w * v0.x;  a0.y = a0.y * corr + w * v0.y;
        a0.z = a0.z * corr + w * v0.z;  a0.w = a0.w * corr + w * v0.w;
        a1.x = a1.x * corr + w * v1.x;  a1.y = a1.y * corr + w * v1.y;
        a1.z = a1.z * corr + w * v1.z;  a1.w = a1.w * corr + w * v1.w;
        m = mn;
    }

    float inv = (cnt > 0) ? 1.f / z : 0.f;
    float* dst = out + (size_t)d * 256 + off;
    float4 o0 = make_float4(a0.x * inv, a0.y * inv, a0.z * inv, a0.w * inv);
    float4 o1 = make_float4(a1.x * inv, a1.y * inv, a1.z * inv, a1.w * inv);
    *reinterpret_cast<float4*>(dst)     = o0;
    *reinterpret_cast<float4*>(dst + 4) = o1;
}

// ---------------- launch ----------------
extern "C" void kernel_launch(void* const* d_in, const int* in_sizes, int n_in,
                              void* d_out, int out_size) {
    const float* x  = (const float*)d_in[0];
    const float* Wq = (const float*)d_in[1];
    const float* bq = (const float*)d_in[2];
    const float* Wk = (const float*)d_in[3];
    const float* bk = (const float*)d_in[4];
    const float* Wv = (const float*)d_in[5];
    const float* bv = (const float*)d_in[6];
    const int* src  = (const int*)d_in[7];
    const int* dst  = (const int*)d_in[8];
    float* out = (float*)d_out;

    size_t nconv = (size_t)NM_PAD * 32;
    convertA_kernel<<<(unsigned)((nconv + 255) / 256), 256>>>(x);
    packB_kernel<<<(KTOT * NINNER + 255) / 256, 256>>>(Wq, bq, Wk, bk, Wv, bv);

    dim3 ggrid(NM_PAD / BM, NINNER / BN);  // 391 x 6
    gemm_mma_kernel<<<ggrid, 256>>>();

    zero_cnt_kernel<<<(NN + 255) / 256, 256>>>();
    scatter_kernel<<<(NE + 255) / 256, 256>>>(src, dst);

    attn_kernel<<<(NN + 7) / 8, 256>>>(out);
}

// round 5
// speedup vs baseline: 2.3700x; 1.1520x over previous
#include <cuda_runtime.h>
#include <cuda_bf16.h>
#include <cuda_fp16.h>
#include <math_constants.h>
#include <cstdint>

#define NN 50000
#define NM_PAD 50048          // 391 * 128
#define NE 800000
#define DIM 256
#define NINNER 768
#define CAP 128

#define BM 128
#define BN 128
#define BK 32
#define KTOT 768              // effective K: [Xhi(256)|Xlo(256)|Xhi(256 again)]
#define NKT (KTOT / BK)       // 24
#define LDA 40
#define LDB 136

// ---------------- device scratch ----------------
__device__ float g_bias[NINNER];
__device__ float g_K[(size_t)NN * 256];               // k fp32
__device__ __half g_QV[(size_t)NN * 512];             // [q(256)|v(256)] fp16, 51MB (L2-resident)
__device__ int   g_cnt[NN];
__device__ int   g_adj[(size_t)NN * CAP];
__device__ __nv_bfloat16 g_A2[(size_t)NM_PAD * 512];  // [m][0:256)=Xhi, [256:512)=Xlo
__device__ __nv_bfloat16 g_B2[(size_t)KTOT * NINNER];

// ---------------- helpers ----------------
__device__ __forceinline__ uint32_t smem_u32(const void* p) {
    uint32_t a;
    asm("{ .reg .u64 t; cvta.to.shared.u64 t, %1; cvt.u32.u64 %0, t; }" : "=r"(a) : "l"(p));
    return a;
}
__device__ __forceinline__ void cp16(uint32_t sdst, const void* gsrc) {
    asm volatile("cp.async.cg.shared.global [%0], [%1], 16;" :: "r"(sdst), "l"(gsrc));
}
__device__ __forceinline__ void cp_commit() { asm volatile("cp.async.commit_group;"); }
template<int N> __device__ __forceinline__ void cp_wait() {
    asm volatile("cp.async.wait_group %0;" :: "n"(N));
}
__device__ __forceinline__ void ldm_x4(uint32_t* r, uint32_t addr) {
    asm volatile("ldmatrix.sync.aligned.m8n8.x4.shared.b16 {%0,%1,%2,%3}, [%4];"
        : "=r"(r[0]), "=r"(r[1]), "=r"(r[2]), "=r"(r[3]) : "r"(addr));
}
__device__ __forceinline__ void ldm_x4t(uint32_t* r, uint32_t addr) {
    asm volatile("ldmatrix.sync.aligned.m8n8.x4.trans.shared.b16 {%0,%1,%2,%3}, [%4];"
        : "=r"(r[0]), "=r"(r[1]), "=r"(r[2]), "=r"(r[3]) : "r"(addr));
}
__device__ __forceinline__ void mma_bf16(float* d, const uint32_t* a, const uint32_t* b) {
    asm volatile(
        "mma.sync.aligned.m16n8k16.row.col.f32.bf16.bf16.f32 "
        "{%0,%1,%2,%3}, {%4,%5,%6,%7}, {%8,%9}, {%0,%1,%2,%3};"
        : "+f"(d[0]), "+f"(d[1]), "+f"(d[2]), "+f"(d[3])
        : "r"(a[0]), "r"(a[1]), "r"(a[2]), "r"(a[3]), "r"(b[0]), "r"(b[1]));
}

// ---------------- kernel 1: X -> split bf16 A2 (+ zero g_cnt) ----------------
__global__ __launch_bounds__(256) void convertA_kernel(const float* __restrict__ X) {
    size_t t = (size_t)blockIdx.x * blockDim.x + threadIdx.x;
    if (t < NN) g_cnt[t] = 0;
    if (t >= (size_t)NM_PAD * 32) return;
    int u = (int)(t & 31);
    int m = (int)(t >> 5);
    __nv_bfloat16 hi[8], lo[8];
    if (m < NN) {
        const float* src = X + (size_t)m * DIM + u * 8;
        float4 v0 = *reinterpret_cast<const float4*>(src);
        float4 v1 = *reinterpret_cast<const float4*>(src + 4);
        float vals[8] = {v0.x, v0.y, v0.z, v0.w, v1.x, v1.y, v1.z, v1.w};
#pragma unroll
        for (int j = 0; j < 8; j++) {
            hi[j] = __float2bfloat16(vals[j]);
            lo[j] = __float2bfloat16(vals[j] - __bfloat162float(hi[j]));
        }
    } else {
#pragma unroll
        for (int j = 0; j < 8; j++) { hi[j] = __float2bfloat16(0.f); lo[j] = __float2bfloat16(0.f); }
    }
    __nv_bfloat16* base = g_A2 + (size_t)m * 512;
    *reinterpret_cast<uint4*>(base + u * 8)       = *reinterpret_cast<uint4*>(hi);
    *reinterpret_cast<uint4*>(base + 256 + u * 8) = *reinterpret_cast<uint4*>(lo);
}

// ---------------- kernel 2: W -> split bf16 B2 + bias ----------------
__global__ __launch_bounds__(256) void packB_kernel(const float* __restrict__ Wq, const float* __restrict__ bq,
                                                    const float* __restrict__ Wk, const float* __restrict__ bk,
                                                    const float* __restrict__ Wv, const float* __restrict__ bv) {
    int t = blockIdx.x * blockDim.x + threadIdx.x;
    if (t < NINNER)
        g_bias[t] = (t < 256) ? bq[t] : (t < 512) ? bk[t - 256] : bv[t - 512];
    if (t >= KTOT * NINNER) return;
    int n = t % NINNER;
    int kc = t / NINNER;
    int k = (kc < 256) ? kc : (kc < 512) ? kc - 256 : kc - 512;
    bool want_lo = (kc >= 512);
    float w = (n < 256) ? Wq[k * 256 + n] : (n < 512) ? Wk[k * 256 + (n - 256)] : Wv[k * 256 + (n - 512)];
    __nv_bfloat16 h = __float2bfloat16(w);
    g_B2[(size_t)kc * NINNER + n] = want_lo ? __float2bfloat16(w - __bfloat162float(h)) : h;
}

// ---------------- kernel 3: bf16 HMMA GEMM -> g_QV (fp16) / g_K (fp32) ----------------
__global__ __launch_bounds__(256) void gemm_mma_kernel() {
    __shared__ __nv_bfloat16 As[2][BM][LDA];
    __shared__ __nv_bfloat16 Bs[2][BK][LDB];

    const int tid = threadIdx.x;
    const int wid = tid >> 5;
    const int lane = tid & 31;
    const int wm = wid & 3;
    const int wn = wid >> 2;
    const int m0 = blockIdx.x * BM;
    const int n0 = blockIdx.y * BN;

    float acc[2][8][4];
#pragma unroll
    for (int i = 0; i < 2; i++)
#pragma unroll
        for (int j = 0; j < 8; j++)
#pragma unroll
            for (int q = 0; q < 4; q++) acc[i][j][q] = 0.f;

    auto load_stage = [&](int st, int kt) {
        int kc = kt * BK;
        int keff = (kc < 512) ? kc : kc - 512;
#pragma unroll
        for (int i = 0; i < 2; i++) {
            int idx = tid + i * 256;
            int r = idx >> 2, kq = idx & 3;
            cp16(smem_u32(&As[st][r][kq * 8]),
                 g_A2 + (size_t)(m0 + r) * 512 + keff + kq * 8);
        }
#pragma unroll
        for (int i = 0; i < 2; i++) {
            int idx = tid + i * 256;
            int r = idx >> 4, cq = idx & 15;
            cp16(smem_u32(&Bs[st][r][cq * 8]),
                 g_B2 + (size_t)(kc + r) * NINNER + n0 + cq * 8);
        }
        cp_commit();
    };

    load_stage(0, 0);

    for (int kt = 0; kt < NKT; kt++) {
        int st = kt & 1;
        if (kt + 1 < NKT) {
            load_stage(st ^ 1, kt + 1);
            cp_wait<1>();
        } else {
            cp_wait<0>();
        }
        __syncthreads();

#pragma unroll
        for (int kk = 0; kk < BK; kk += 16) {
            uint32_t a[2][4], b[4][4];
#pragma unroll
            for (int mi = 0; mi < 2; mi++) {
                int ar = wm * 32 + mi * 16 + (lane & 15);
                int ac = kk + ((lane >> 4) << 3);
                ldm_x4(a[mi], smem_u32(&As[st][ar][ac]));
            }
#pragma unroll
            for (int nt = 0; nt < 4; nt++) {
                int br = kk + (lane & 15);
                int bc = wn * 64 + nt * 16 + ((lane >> 4) << 3);
                ldm_x4t(b[nt], smem_u32(&Bs[st][br][bc]));
            }
#pragma unroll
            for (int mi = 0; mi < 2; mi++)
#pragma unroll
                for (int nj = 0; nj < 8; nj++)
                    mma_bf16(acc[mi][nj], a[mi], &b[nj >> 1][(nj & 1) * 2]);
        }
        __syncthreads();
    }

    // epilogue: route q -> g_QV fp16, k -> g_K fp32, v -> g_QV fp16
#pragma unroll
    for (int mi = 0; mi < 2; mi++) {
        int row0 = m0 + wm * 32 + mi * 16 + (lane >> 2);
#pragma unroll
        for (int nj = 0; nj < 8; nj++) {
            int nc = n0 + wn * 64 + nj * 8 + (lane & 3) * 2;
            float b0 = g_bias[nc], b1 = g_bias[nc + 1];
#pragma unroll
            for (int half_ = 0; half_ < 2; half_++) {
                int row = row0 + half_ * 8;
                if (row >= NN) continue;
                float v0 = acc[mi][nj][half_ * 2 + 0] + b0;
                float v1 = acc[mi][nj][half_ * 2 + 1] + b1;
                if (nc < 256) {
                    __half2 h = __floats2half2_rn(v0, v1);
                    *reinterpret_cast<__half2*>(g_QV + (size_t)row * 512 + nc) = h;
                } else if (nc < 512) {
                    float2 f = make_float2(v0, v1);
                    *reinterpret_cast<float2*>(g_K + (size_t)row * 256 + (nc - 256)) = f;
                } else {
                    __half2 h = __floats2half2_rn(v0, v1);
                    *reinterpret_cast<__half2*>(g_QV + (size_t)row * 512 + 256 + (nc - 512)) = h;
                }
            }
        }
    }
}

// ---------------- kernel 4: scatter edges ----------------
__global__ void scatter_kernel(const int* __restrict__ src, const int* __restrict__ dst) {
    int e = blockIdx.x * blockDim.x + threadIdx.x;
    if (e < NE) {
        int d = dst[e];
        int p = atomicAdd(&g_cnt[d], 1);
        if (p < CAP) g_adj[(size_t)d * CAP + p] = src[e];
    }
}

// ---------------- kernel 5: warp-per-dst attention (fp16 q/v gather) ----------------
__global__ __launch_bounds__(256) void attn_kernel(float* __restrict__ out) {
    const int d = blockIdx.x * 8 + (threadIdx.x >> 5);
    if (d >= NN) return;
    const int lane = threadIdx.x & 31;
    const int off = lane * 8;

    int cnt = g_cnt[d];
    if (cnt > CAP) cnt = CAP;
    const int* adj = &g_adj[(size_t)d * CAP];

    // preload entire adjacency into registers (lane j holds adj[q*32+j])
    int sreg[4];
#pragma unroll
    for (int j = 0; j < 4; j++) {
        int idx = j * 32 + lane;
        sreg[j] = (idx < cnt) ? adj[idx] : 0;
    }

    // dst K slice: 8 fp32
    const float* krow = g_K + (size_t)d * 256 + off;
    float4 k0 = *reinterpret_cast<const float4*>(krow);
    float4 k1 = *reinterpret_cast<const float4*>(krow + 4);

    float m = -CUDART_INF_F;
    float z = 0.f;
    float a[8] = {0.f, 0.f, 0.f, 0.f, 0.f, 0.f, 0.f, 0.f};
    const float scale = 0.17677669529663687f;  // 1/sqrt(32)

    uint4 qr, vr, qn, vn;
    auto fetch = [&](int i, uint4& q_, uint4& v_) {
        int s = __shfl_sync(0xFFFFFFFFu, sreg[i >> 5], i & 31);
        const __half* base = g_QV + (size_t)s * 512 + off;
        q_ = *reinterpret_cast<const uint4*>(base);
        v_ = *reinterpret_cast<const uint4*>(base + 256);
    };

    if (cnt > 0) fetch(0, qr, vr);

    for (int i = 0; i < cnt; i++) {
        if (i + 1 < cnt) fetch(i + 1, qn, vn);

        float2 q0 = __half22float2(*reinterpret_cast<__half2*>(&qr.x));
        float2 q1 = __half22float2(*reinterpret_cast<__half2*>(&qr.y));
        float2 q2 = __half22float2(*reinterpret_cast<__half2*>(&qr.z));
        float2 q3 = __half22float2(*reinterpret_cast<__half2*>(&qr.w));

        float dot = q0.x * k0.x + q0.y * k0.y + q1.x * k0.z + q1.y * k0.w
                  + q2.x * k1.x + q2.y * k1.y + q3.x * k1.z + q3.y * k1.w;
        dot += __shfl_xor_sync(0xFFFFFFFFu, dot, 1);
        dot += __shfl_xor_sync(0xFFFFFFFFu, dot, 2);
        float score = dot * scale;

        float mn = fmaxf(m, score);
        float corr = __expf(m - mn);      // 0 on first edge
        float w = __expf(score - mn);
        z = z * corr + w;

        float2 v0 = __half22float2(*reinterpret_cast<__half2*>(&vr.x));
        float2 v1 = __half22float2(*reinterpret_cast<__half2*>(&vr.y));
        float2 v2 = __half22float2(*reinterpret_cast<__half2*>(&vr.z));
        float2 v3 = __half22float2(*reinterpret_cast<__half2*>(&vr.w));
        a[0] = a[0] * corr + w * v0.x;  a[1] = a[1] * corr + w * v0.y;
        a[2] = a[2] * corr + w * v1.x;  a[3] = a[3] * corr + w * v1.y;
        a[4] = a[4] * corr + w * v2.x;  a[5] = a[5] * corr + w * v2.y;
        a[6] = a[6] * corr + w * v3.x;  a[7] = a[7] * corr + w * v3.y;
        m = mn;

        qr = qn; vr = vn;
    }

    float inv = (cnt > 0) ? 1.f / z : 0.f;
    float* dst = out + (size_t)d * 256 + off;
    float4 o0 = make_float4(a[0] * inv, a[1] * inv, a[2] * inv, a[3] * inv);
    float4 o1 = make_float4(a[4] * inv, a[5] * inv, a[6] * inv, a[7] * inv);
    *reinterpret_cast<float4*>(dst)     = o0;
    *reinterpret_cast<float4*>(dst + 4) = o1;
}

// ---------------- launch ----------------
extern "C" void kernel_launch(void* const* d_in, const int* in_sizes, int n_in,
                              void* d_out, int out_size) {
    const float* x  = (const float*)d_in[0];
    const float* Wq = (const float*)d_in[1];
    const float* bq = (const float*)d_in[2];
    const float* Wk = (const float*)d_in[3];
    const float* bk = (const float*)d_in[4];
    const float* Wv = (const float*)d_in[5];
    const float* bv = (const float*)d_in[6];
    const int* src  = (const int*)d_in[7];
    const int* dst  = (const int*)d_in[8];
    float* out = (float*)d_out;

    size_t nconv = (size_t)NM_PAD * 32;
    convertA_kernel<<<(unsigned)((nconv + 255) / 256), 256>>>(x);
    packB_kernel<<<(KTOT * NINNER + 255) / 256, 256>>>(Wq, bq, Wk, bk, Wv, bv);

    dim3 ggrid(NM_PAD / BM, NINNER / BN);  // 391 x 6
    gemm_mma_kernel<<<ggrid, 256>>>();

    scatter_kernel<<<(NE + 255) / 256, 256>>>(src, dst);

    attn_kernel<<<(NN + 7) / 8, 256>>>(out);
}

// round 6
// speedup vs baseline: 2.7859x; 1.1755x over previous
#include <cuda_runtime.h>
#include <cuda_fp16.h>
#include <math_constants.h>
#include <cstdint>

#define NN 50000
#define NM_PAD 50048          // 391 * 128
#define NE 800000
#define DIM 256
#define NINNER 768
#define CAP 128

#define BM 128
#define BN 128
#define BK 32
#define KTOT 512              // [W_hi(256); W_lo(256)] ; A is single fp16, read twice
#define NKT (KTOT / BK)       // 16
#define NST 4                 // pipeline stages
#define LDA 40                // As row stride (halves): 80B, conflict-free ldmatrix
#define LDB 136               // Bs row stride (halves): 272B, conflict-free trans ldmatrix

#define ABYTES (BM * LDA * 2)             // 10240
#define BBYTES (BK * LDB * 2)             // 8704
#define STAGE_BYTES (ABYTES + BBYTES)     // 18944
#define SMEM_TOTAL (NST * STAGE_BYTES)    // 75776

// ---------------- device scratch ----------------
__device__ float g_bias[NINNER];
__device__ float g_K[(size_t)NN * 256];               // k fp32
__device__ __half g_QV[(size_t)NN * 512];             // [q(256)|v(256)] fp16 (L2-resident)
__device__ int   g_cnt[NN];
__device__ int   g_adj[(size_t)NN * CAP];
__device__ __half g_A2[(size_t)NM_PAD * 256];         // X in fp16
__device__ __half g_B2[(size_t)KTOT * NINNER];        // rows 0-255 Whi, 256-511 Wlo

// ---------------- helpers ----------------
__device__ __forceinline__ uint32_t smem_u32(const void* p) {
    uint32_t a;
    asm("{ .reg .u64 t; cvta.to.shared.u64 t, %1; cvt.u32.u64 %0, t; }" : "=r"(a) : "l"(p));
    return a;
}
__device__ __forceinline__ void cp16(uint32_t sdst, const void* gsrc) {
    asm volatile("cp.async.cg.shared.global [%0], [%1], 16;" :: "r"(sdst), "l"(gsrc));
}
__device__ __forceinline__ void cp_commit() { asm volatile("cp.async.commit_group;"); }
template<int N> __device__ __forceinline__ void cp_wait() {
    asm volatile("cp.async.wait_group %0;" :: "n"(N));
}
__device__ __forceinline__ void ldm_x4(uint32_t* r, uint32_t addr) {
    asm volatile("ldmatrix.sync.aligned.m8n8.x4.shared.b16 {%0,%1,%2,%3}, [%4];"
        : "=r"(r[0]), "=r"(r[1]), "=r"(r[2]), "=r"(r[3]) : "r"(addr));
}
__device__ __forceinline__ void ldm_x4t(uint32_t* r, uint32_t addr) {
    asm volatile("ldmatrix.sync.aligned.m8n8.x4.trans.shared.b16 {%0,%1,%2,%3}, [%4];"
        : "=r"(r[0]), "=r"(r[1]), "=r"(r[2]), "=r"(r[3]) : "r"(addr));
}
__device__ __forceinline__ void mma_f16(float* d, const uint32_t* a, const uint32_t* b) {
    asm volatile(
        "mma.sync.aligned.m16n8k16.row.col.f32.f16.f16.f32 "
        "{%0,%1,%2,%3}, {%4,%5,%6,%7}, {%8,%9}, {%0,%1,%2,%3};"
        : "+f"(d[0]), "+f"(d[1]), "+f"(d[2]), "+f"(d[3])
        : "r"(a[0]), "r"(a[1]), "r"(a[2]), "r"(a[3]), "r"(b[0]), "r"(b[1]));
}

// ---------------- kernel 1: X -> fp16 A2 (+ zero g_cnt) ----------------
__global__ __launch_bounds__(256) void convertA_kernel(const float* __restrict__ X) {
    size_t t = (size_t)blockIdx.x * blockDim.x + threadIdx.x;
    if (t < NN) g_cnt[t] = 0;
    if (t >= (size_t)NM_PAD * 32) return;
    int u = (int)(t & 31);
    int m = (int)(t >> 5);
    __half h[8];
    if (m < NN) {
        const float* src = X + (size_t)m * DIM + u * 8;
        float4 v0 = *reinterpret_cast<const float4*>(src);
        float4 v1 = *reinterpret_cast<const float4*>(src + 4);
        h[0] = __float2half_rn(v0.x); h[1] = __float2half_rn(v0.y);
        h[2] = __float2half_rn(v0.z); h[3] = __float2half_rn(v0.w);
        h[4] = __float2half_rn(v1.x); h[5] = __float2half_rn(v1.y);
        h[6] = __float2half_rn(v1.z); h[7] = __float2half_rn(v1.w);
    } else {
#pragma unroll
        for (int j = 0; j < 8; j++) h[j] = __float2half_rn(0.f);
    }
    *reinterpret_cast<uint4*>(g_A2 + (size_t)m * 256 + u * 8) = *reinterpret_cast<uint4*>(h);
}

// ---------------- kernel 2: W -> fp16 split B2 + bias ----------------
__global__ __launch_bounds__(256) void packB_kernel(const float* __restrict__ Wq, const float* __restrict__ bq,
                                                    const float* __restrict__ Wk, const float* __restrict__ bk,
                                                    const float* __restrict__ Wv, const float* __restrict__ bv) {
    int t = blockIdx.x * blockDim.x + threadIdx.x;
    if (t < NINNER)
        g_bias[t] = (t < 256) ? bq[t] : (t < 512) ? bk[t - 256] : bv[t - 512];
    if (t >= 256 * NINNER) return;
    int n = t % NINNER;
    int k = t / NINNER;
    float w = (n < 256) ? Wq[k * 256 + n] : (n < 512) ? Wk[k * 256 + (n - 256)] : Wv[k * 256 + (n - 512)];
    __half hi = __float2half_rn(w);
    __half lo = __float2half_rn(w - __half2float(hi));
    g_B2[(size_t)k * NINNER + n]         = hi;
    g_B2[(size_t)(k + 256) * NINNER + n] = lo;
}

// ---------------- kernel 3: fp16 HMMA GEMM -> g_QV (fp16) / g_K (fp32) ----------------
__global__ __launch_bounds__(256) void gemm_mma_kernel() {
    extern __shared__ char smem[];

    const int tid = threadIdx.x;
    const int wid = tid >> 5;
    const int lane = tid & 31;
    const int wm = wid & 3;
    const int wn = wid >> 2;
    const int m0 = blockIdx.x * BM;
    const int n0 = blockIdx.y * BN;

    float acc[2][8][4];
#pragma unroll
    for (int i = 0; i < 2; i++)
#pragma unroll
        for (int j = 0; j < 8; j++)
#pragma unroll
            for (int q = 0; q < 4; q++) acc[i][j][q] = 0.f;

    auto As = [&](int st) { return reinterpret_cast<__half*>(smem + st * STAGE_BYTES); };
    auto Bs = [&](int st) { return reinterpret_cast<__half*>(smem + st * STAGE_BYTES + ABYTES); };

    auto load_stage = [&](int st, int kt) {
        int kc = kt * BK;
        int keff = kc & 255;              // A has K=256, read twice
        __half* as = As(st);
        __half* bs = Bs(st);
#pragma unroll
        for (int i = 0; i < 2; i++) {
            int idx = tid + i * 256;
            int r = idx >> 2, kq = idx & 3;
            cp16(smem_u32(as + r * LDA + kq * 8),
                 g_A2 + (size_t)(m0 + r) * 256 + keff + kq * 8);
        }
#pragma unroll
        for (int i = 0; i < 2; i++) {
            int idx = tid + i * 256;
            int r = idx >> 4, cq = idx & 15;
            cp16(smem_u32(bs + r * LDB + cq * 8),
                 g_B2 + (size_t)(kc + r) * NINNER + n0 + cq * 8);
        }
        cp_commit();
    };

    load_stage(0, 0);
    load_stage(1, 1);
    load_stage(2, 2);

    for (int kt = 0; kt < NKT; kt++) {
        int st = kt & 3;
        cp_wait<2>();                      // stage kt's group complete
        __syncthreads();
        if (kt + 3 < NKT) load_stage((kt + 3) & 3, kt + 3);

        __half* as = As(st);
        __half* bs = Bs(st);
#pragma unroll
        for (int kk = 0; kk < BK; kk += 16) {
            uint32_t a[2][4], b[4][4];
#pragma unroll
            for (int mi = 0; mi < 2; mi++) {
                int ar = wm * 32 + mi * 16 + (lane & 15);
                int ac = kk + ((lane >> 4) << 3);
                ldm_x4(a[mi], smem_u32(as + ar * LDA + ac));
            }
#pragma unroll
            for (int nt = 0; nt < 4; nt++) {
                int br = kk + (lane & 15);
                int bc = wn * 64 + nt * 16 + ((lane >> 4) << 3);
                ldm_x4t(b[nt], smem_u32(bs + br * LDB + bc));
            }
#pragma unroll
            for (int mi = 0; mi < 2; mi++)
#pragma unroll
                for (int nj = 0; nj < 8; nj++)
                    mma_f16(acc[mi][nj], a[mi], &b[nj >> 1][(nj & 1) * 2]);
        }
    }

    // epilogue: route q -> g_QV fp16, k -> g_K fp32, v -> g_QV fp16
#pragma unroll
    for (int mi = 0; mi < 2; mi++) {
        int row0 = m0 + wm * 32 + mi * 16 + (lane >> 2);
#pragma unroll
        for (int nj = 0; nj < 8; nj++) {
            int nc = n0 + wn * 64 + nj * 8 + (lane & 3) * 2;
            float b0 = g_bias[nc], b1 = g_bias[nc + 1];
#pragma unroll
            for (int half_ = 0; half_ < 2; half_++) {
                int row = row0 + half_ * 8;
                if (row >= NN) continue;
                float v0 = acc[mi][nj][half_ * 2 + 0] + b0;
                float v1 = acc[mi][nj][half_ * 2 + 1] + b1;
                if (nc < 256) {
                    *reinterpret_cast<__half2*>(g_QV + (size_t)row * 512 + nc) = __floats2half2_rn(v0, v1);
                } else if (nc < 512) {
                    *reinterpret_cast<float2*>(g_K + (size_t)row * 256 + (nc - 256)) = make_float2(v0, v1);
                } else {
                    *reinterpret_cast<__half2*>(g_QV + (size_t)row * 512 + 256 + (nc - 512)) = __floats2half2_rn(v0, v1);
                }
            }
        }
    }
}

// ---------------- kernel 4: scatter edges ----------------
__global__ void scatter_kernel(const int* __restrict__ src, const int* __restrict__ dst) {
    int e = blockIdx.x * blockDim.x + threadIdx.x;
    if (e < NE) {
        int d = dst[e];
        int p = atomicAdd(&g_cnt[d], 1);
        if (p < CAP) g_adj[(size_t)d * CAP + p] = src[e];
    }
}

// ---------------- kernel 5: warp-per-dst attention (fp16 q/v gather) ----------------
__global__ __launch_bounds__(256) void attn_kernel(float* __restrict__ out) {
    const int d = blockIdx.x * 8 + (threadIdx.x >> 5);
    if (d >= NN) return;
    const int lane = threadIdx.x & 31;
    const int off = lane * 8;

    int cnt = g_cnt[d];
    if (cnt > CAP) cnt = CAP;
    const int* adj = &g_adj[(size_t)d * CAP];

    int sreg[4];
#pragma unroll
    for (int j = 0; j < 4; j++) {
        int idx = j * 32 + lane;
        sreg[j] = (idx < cnt) ? adj[idx] : 0;
    }

    const float* krow = g_K + (size_t)d * 256 + off;
    float4 k0 = *reinterpret_cast<const float4*>(krow);
    float4 k1 = *reinterpret_cast<const float4*>(krow + 4);

    float m = -CUDART_INF_F;
    float z = 0.f;
    float a[8] = {0.f, 0.f, 0.f, 0.f, 0.f, 0.f, 0.f, 0.f};
    const float scale = 0.17677669529663687f;  // 1/sqrt(32)

    uint4 qr, vr, qn, vn;
    auto fetch = [&](int i, uint4& q_, uint4& v_) {
        int s = __shfl_sync(0xFFFFFFFFu, sreg[i >> 5], i & 31);
        const __half* base = g_QV + (size_t)s * 512 + off;
        q_ = *reinterpret_cast<const uint4*>(base);
        v_ = *reinterpret_cast<const uint4*>(base + 256);
    };

    if (cnt > 0) fetch(0, qr, vr);

    for (int i = 0; i < cnt; i++) {
        if (i + 1 < cnt) fetch(i + 1, qn, vn);

        float2 q0 = __half22float2(*reinterpret_cast<__half2*>(&qr.x));
        float2 q1 = __half22float2(*reinterpret_cast<__half2*>(&qr.y));
        float2 q2 = __half22float2(*reinterpret_cast<__half2*>(&qr.z));
        float2 q3 = __half22float2(*reinterpret_cast<__half2*>(&qr.w));

        float dot = q0.x * k0.x + q0.y * k0.y + q1.x * k0.z + q1.y * k0.w
                  + q2.x * k1.x + q2.y * k1.y + q3.x * k1.z + q3.y * k1.w;
        dot += __shfl_xor_sync(0xFFFFFFFFu, dot, 1);
        dot += __shfl_xor_sync(0xFFFFFFFFu, dot, 2);
        float score = dot * scale;

        float mn = fmaxf(m, score);
        float corr = __expf(m - mn);
        float w = __expf(score - mn);
        z = z * corr + w;

        float2 v0 = __half22float2(*reinterpret_cast<__half2*>(&vr.x));
        float2 v1 = __half22float2(*reinterpret_cast<__half2*>(&vr.y));
        float2 v2 = __half22float2(*reinterpret_cast<__half2*>(&vr.z));
        float2 v3 = __half22float2(*reinterpret_cast<__half2*>(&vr.w));
        a[0] = a[0] * corr + w * v0.x;  a[1] = a[1] * corr + w * v0.y;
        a[2] = a[2] * corr + w * v1.x;  a[3] = a[3] * corr + w * v1.y;
        a[4] = a[4] * corr + w * v2.x;  a[5] = a[5] * corr + w * v2.y;
        a[6] = a[6] * corr + w * v3.x;  a[7] = a[7] * corr + w * v3.y;
        m = mn;

        qr = qn; vr = vn;
    }

    float inv = (cnt > 0) ? 1.f / z : 0.f;
    float* dst = out + (size_t)d * 256 + off;
    *reinterpret_cast<float4*>(dst)     = make_float4(a[0] * inv, a[1] * inv, a[2] * inv, a[3] * inv);
    *reinterpret_cast<float4*>(dst + 4) = make_float4(a[4] * inv, a[5] * inv, a[6] * inv, a[7] * inv);
}

// ---------------- launch ----------------
extern "C" void kernel_launch(void* const* d_in, const int* in_sizes, int n_in,
                              void* d_out, int out_size) {
    const float* x  = (const float*)d_in[0];
    const float* Wq = (const float*)d_in[1];
    const float* bq = (const float*)d_in[2];
    const float* Wk = (const float*)d_in[3];
    const float* bk = (const float*)d_in[4];
    const float* Wv = (const float*)d_in[5];
    const float* bv = (const float*)d_in[6];
    const int* src  = (const int*)d_in[7];
    const int* dst  = (const int*)d_in[8];
    float* out = (float*)d_out;

    cudaFuncSetAttribute(gemm_mma_kernel, cudaFuncAttributeMaxDynamicSharedMemorySize, SMEM_TOTAL);

    size_t nconv = (size_t)NM_PAD * 32;
    convertA_kernel<<<(unsigned)((nconv + 255) / 256), 256>>>(x);
    packB_kernel<<<(256 * NINNER + 255) / 256, 256>>>(Wq, bq, Wk, bk, Wv, bv);

    dim3 ggrid(NM_PAD / BM, NINNER / BN);  // 391 x 6
    gemm_mma_kernel<<<ggrid, 256, SMEM_TOTAL>>>();

    scatter_kernel<<<(NE + 255) / 256, 256>>>(src, dst);

    attn_kernel<<<(NN + 7) / 8, 256>>>(out);
}

// round 7
// speedup vs baseline: 3.6752x; 1.3192x over previous
#include <cuda_runtime.h>
#include <cuda_fp16.h>
#include <math_constants.h>
#include <cstdint>

#define NN 50000
#define NM_PAD 50048          // 391 * 128
#define NE 800000
#define DIM 256
#define NINNER 768
#define CAP 128

#define BM 128
#define BN 128
#define BK 32
#define KTOT 256              // plain fp16 X @ fp16 W
#define NKT (KTOT / BK)       // 8
#define NST 4                 // pipeline stages
#define LDA 40                // As row stride (halves): 80B, conflict-free ldmatrix
#define LDB 136               // Bs row stride (halves): 272B, conflict-free trans ldmatrix

#define ABYTES (BM * LDA * 2)             // 10240
#define BBYTES (BK * LDB * 2)             // 8704
#define STAGE_BYTES (ABYTES + BBYTES)     // 18944
#define SMEM_TOTAL (NST * STAGE_BYTES)    // 75776

// ---------------- device scratch ----------------
__device__ float g_bias[NINNER];
__device__ float g_K[(size_t)NN * 256];               // k fp32
__device__ __half g_QV[(size_t)NN * 512];             // [q(256)|v(256)] fp16 (L2-resident)
__device__ int   g_cnt[NN];
__device__ int   g_adj[(size_t)NN * CAP];
__device__ __half g_A2[(size_t)NM_PAD * 256];         // X in fp16
__device__ __half g_B2[(size_t)KTOT * NINNER];        // W in fp16

// ---------------- helpers ----------------
__device__ __forceinline__ uint32_t smem_u32(const void* p) {
    uint32_t a;
    asm("{ .reg .u64 t; cvta.to.shared.u64 t, %1; cvt.u32.u64 %0, t; }" : "=r"(a) : "l"(p));
    return a;
}
__device__ __forceinline__ void cp16(uint32_t sdst, const void* gsrc) {
    asm volatile("cp.async.cg.shared.global [%0], [%1], 16;" :: "r"(sdst), "l"(gsrc));
}
__device__ __forceinline__ void cp_commit() { asm volatile("cp.async.commit_group;"); }
template<int N> __device__ __forceinline__ void cp_wait() {
    asm volatile("cp.async.wait_group %0;" :: "n"(N));
}
__device__ __forceinline__ void ldm_x4(uint32_t* r, uint32_t addr) {
    asm volatile("ldmatrix.sync.aligned.m8n8.x4.shared.b16 {%0,%1,%2,%3}, [%4];"
        : "=r"(r[0]), "=r"(r[1]), "=r"(r[2]), "=r"(r[3]) : "r"(addr));
}
__device__ __forceinline__ void ldm_x4t(uint32_t* r, uint32_t addr) {
    asm volatile("ldmatrix.sync.aligned.m8n8.x4.trans.shared.b16 {%0,%1,%2,%3}, [%4];"
        : "=r"(r[0]), "=r"(r[1]), "=r"(r[2]), "=r"(r[3]) : "r"(addr));
}
__device__ __forceinline__ void mma_f16(float* d, const uint32_t* a, const uint32_t* b) {
    asm volatile(
        "mma.sync.aligned.m16n8k16.row.col.f32.f16.f16.f32 "
        "{%0,%1,%2,%3}, {%4,%5,%6,%7}, {%8,%9}, {%0,%1,%2,%3};"
        : "+f"(d[0]), "+f"(d[1]), "+f"(d[2]), "+f"(d[3])
        : "r"(a[0]), "r"(a[1]), "r"(a[2]), "r"(a[3]), "r"(b[0]), "r"(b[1]));
}

// ---------------- kernel 1: X -> fp16 A2 (+ zero g_cnt) ----------------
__global__ __launch_bounds__(256) void convertA_kernel(const float* __restrict__ X) {
    size_t t = (size_t)blockIdx.x * blockDim.x + threadIdx.x;
    if (t < NN) g_cnt[t] = 0;
    if (t >= (size_t)NM_PAD * 32) return;
    int u = (int)(t & 31);
    int m = (int)(t >> 5);
    __half h[8];
    if (m < NN) {
        const float* src = X + (size_t)m * DIM + u * 8;
        float4 v0 = *reinterpret_cast<const float4*>(src);
        float4 v1 = *reinterpret_cast<const float4*>(src + 4);
        h[0] = __float2half_rn(v0.x); h[1] = __float2half_rn(v0.y);
        h[2] = __float2half_rn(v0.z); h[3] = __float2half_rn(v0.w);
        h[4] = __float2half_rn(v1.x); h[5] = __float2half_rn(v1.y);
        h[6] = __float2half_rn(v1.z); h[7] = __float2half_rn(v1.w);
    } else {
#pragma unroll
        for (int j = 0; j < 8; j++) h[j] = __float2half_rn(0.f);
    }
    *reinterpret_cast<uint4*>(g_A2 + (size_t)m * 256 + u * 8) = *reinterpret_cast<uint4*>(h);
}

// ---------------- kernel 2: W -> fp16 B2 + bias ----------------
__global__ __launch_bounds__(256) void packB_kernel(const float* __restrict__ Wq, const float* __restrict__ bq,
                                                    const float* __restrict__ Wk, const float* __restrict__ bk,
                                                    const float* __restrict__ Wv, const float* __restrict__ bv) {
    int t = blockIdx.x * blockDim.x + threadIdx.x;
    if (t < NINNER)
        g_bias[t] = (t < 256) ? bq[t] : (t < 512) ? bk[t - 256] : bv[t - 512];
    if (t >= 256 * NINNER) return;
    int n = t % NINNER;
    int k = t / NINNER;
    float w = (n < 256) ? Wq[k * 256 + n] : (n < 512) ? Wk[k * 256 + (n - 256)] : Wv[k * 256 + (n - 512)];
    g_B2[(size_t)k * NINNER + n] = __float2half_rn(w);
}

// ---------------- kernel 3: fp16 HMMA GEMM -> g_QV (fp16) / g_K (fp32) ----------------
__global__ __launch_bounds__(256) void gemm_mma_kernel() {
    extern __shared__ char smem[];

    const int tid = threadIdx.x;
    const int wid = tid >> 5;
    const int lane = tid & 31;
    const int wm = wid & 3;
    const int wn = wid >> 2;
    const int m0 = blockIdx.x * BM;
    const int n0 = blockIdx.y * BN;

    float acc[2][8][4];
#pragma unroll
    for (int i = 0; i < 2; i++)
#pragma unroll
        for (int j = 0; j < 8; j++)
#pragma unroll
            for (int q = 0; q < 4; q++) acc[i][j][q] = 0.f;

    auto As = [&](int st) { return reinterpret_cast<__half*>(smem + st * STAGE_BYTES); };
    auto Bs = [&](int st) { return reinterpret_cast<__half*>(smem + st * STAGE_BYTES + ABYTES); };

    auto load_stage = [&](int st, int kt) {
        int kc = kt * BK;
        __half* as = As(st);
        __half* bs = Bs(st);
#pragma unroll
        for (int i = 0; i < 2; i++) {
            int idx = tid + i * 256;
            int r = idx >> 2, kq = idx & 3;
            cp16(smem_u32(as + r * LDA + kq * 8),
                 g_A2 + (size_t)(m0 + r) * 256 + kc + kq * 8);
        }
#pragma unroll
        for (int i = 0; i < 2; i++) {
            int idx = tid + i * 256;
            int r = idx >> 4, cq = idx & 15;
            cp16(smem_u32(bs + r * LDB + cq * 8),
                 g_B2 + (size_t)(kc + r) * NINNER + n0 + cq * 8);
        }
        cp_commit();
    };

    load_stage(0, 0);
    load_stage(1, 1);
    load_stage(2, 2);

    for (int kt = 0; kt < NKT; kt++) {
        int st = kt & 3;
        cp_wait<2>();
        __syncthreads();
        if (kt + 3 < NKT) load_stage((kt + 3) & 3, kt + 3);

        __half* as = As(st);
        __half* bs = Bs(st);
#pragma unroll
        for (int kk = 0; kk < BK; kk += 16) {
            uint32_t a[2][4], b[4][4];
#pragma unroll
            for (int mi = 0; mi < 2; mi++) {
                int ar = wm * 32 + mi * 16 + (lane & 15);
                int ac = kk + ((lane >> 4) << 3);
                ldm_x4(a[mi], smem_u32(as + ar * LDA + ac));
            }
#pragma unroll
            for (int nt = 0; nt < 4; nt++) {
                int br = kk + (lane & 15);
                int bc = wn * 64 + nt * 16 + ((lane >> 4) << 3);
                ldm_x4t(b[nt], smem_u32(bs + br * LDB + bc));
            }
#pragma unroll
            for (int mi = 0; mi < 2; mi++)
#pragma unroll
                for (int nj = 0; nj < 8; nj++)
                    mma_f16(acc[mi][nj], a[mi], &b[nj >> 1][(nj & 1) * 2]);
        }
    }

    // epilogue: route q -> g_QV fp16, k -> g_K fp32, v -> g_QV fp16
#pragma unroll
    for (int mi = 0; mi < 2; mi++) {
        int row0 = m0 + wm * 32 + mi * 16 + (lane >> 2);
#pragma unroll
        for (int nj = 0; nj < 8; nj++) {
            int nc = n0 + wn * 64 + nj * 8 + (lane & 3) * 2;
            float b0 = g_bias[nc], b1 = g_bias[nc + 1];
#pragma unroll
            for (int half_ = 0; half_ < 2; half_++) {
                int row = row0 + half_ * 8;
                if (row >= NN) continue;
                float v0 = acc[mi][nj][half_ * 2 + 0] + b0;
                float v1 = acc[mi][nj][half_ * 2 + 1] + b1;
                if (nc < 256) {
                    *reinterpret_cast<__half2*>(g_QV + (size_t)row * 512 + nc) = __floats2half2_rn(v0, v1);
                } else if (nc < 512) {
                    *reinterpret_cast<float2*>(g_K + (size_t)row * 256 + (nc - 256)) = make_float2(v0, v1);
                } else {
                    *reinterpret_cast<__half2*>(g_QV + (size_t)row * 512 + 256 + (nc - 512)) = __floats2half2_rn(v0, v1);
                }
            }
        }
    }
}

// ---------------- kernel 4: scatter edges ----------------
__global__ void scatter_kernel(const int* __restrict__ src, const int* __restrict__ dst) {
    int e = blockIdx.x * blockDim.x + threadIdx.x;
    if (e < NE) {
        int d = dst[e];
        int p = atomicAdd(&g_cnt[d], 1);
        if (p < CAP) g_adj[(size_t)d * CAP + p] = src[e];
    }
}

// ---------------- kernel 5: warp-per-dst attention (fp16 q/v gather) ----------------
__global__ __launch_bounds__(256) void attn_kernel(float* __restrict__ out) {
    const int d = blockIdx.x * 8 + (threadIdx.x >> 5);
    if (d >= NN) return;
    const int lane = threadIdx.x & 31;
    const int off = lane * 8;

    int cnt = g_cnt[d];
    if (cnt > CAP) cnt = CAP;
    const int* adj = &g_adj[(size_t)d * CAP];

    int sreg[4];
#pragma unroll
    for (int j = 0; j < 4; j++) {
        int idx = j * 32 + lane;
        sreg[j] = (idx < cnt) ? adj[idx] : 0;
    }

    const float* krow = g_K + (size_t)d * 256 + off;
    float4 k0 = *reinterpret_cast<const float4*>(krow);
    float4 k1 = *reinterpret_cast<const float4*>(krow + 4);

    float m = -CUDART_INF_F;
    float z = 0.f;
    float a[8] = {0.f, 0.f, 0.f, 0.f, 0.f, 0.f, 0.f, 0.f};
    const float scale = 0.17677669529663687f;  // 1/sqrt(32)

    uint4 qr, vr, qn, vn;
    auto fetch = [&](int i, uint4& q_, uint4& v_) {
        int s = __shfl_sync(0xFFFFFFFFu, sreg[i >> 5], i & 31);
        const __half* base = g_QV + (size_t)s * 512 + off;
        q_ = *reinterpret_cast<const uint4*>(base);
        v_ = *reinterpret_cast<const uint4*>(base + 256);
    };

    if (cnt > 0) fetch(0, qr, vr);

    for (int i = 0; i < cnt; i++) {
        if (i + 1 < cnt) fetch(i + 1, qn, vn);

        float2 q0 = __half22float2(*reinterpret_cast<__half2*>(&qr.x));
        float2 q1 = __half22float2(*reinterpret_cast<__half2*>(&qr.y));
        float2 q2 = __half22float2(*reinterpret_cast<__half2*>(&qr.z));
        float2 q3 = __half22float2(*reinterpret_cast<__half2*>(&qr.w));

        float dot = q0.x * k0.x + q0.y * k0.y + q1.x * k0.z + q1.y * k0.w
                  + q2.x * k1.x + q2.y * k1.y + q3.x * k1.z + q3.y * k1.w;
        dot += __shfl_xor_sync(0xFFFFFFFFu, dot, 1);
        dot += __shfl_xor_sync(0xFFFFFFFFu, dot, 2);
        float score = dot * scale;

        float mn = fmaxf(m, score);
        float corr = __expf(m - mn);
        float w = __expf(score - mn);
        z = z * corr + w;

        float2 v0 = __half22float2(*reinterpret_cast<__half2*>(&vr.x));
        float2 v1 = __half22float2(*reinterpret_cast<__half2*>(&vr.y));
        float2 v2 = __half22float2(*reinterpret_cast<__half2*>(&vr.z));
        float2 v3 = __half22float2(*reinterpret_cast<__half2*>(&vr.w));
        a[0] = a[0] * corr + w * v0.x;  a[1] = a[1] * corr + w * v0.y;
        a[2] = a[2] * corr + w * v1.x;  a[3] = a[3] * corr + w * v1.y;
        a[4] = a[4] * corr + w * v2.x;  a[5] = a[5] * corr + w * v2.y;
        a[6] = a[6] * corr + w * v3.x;  a[7] = a[7] * corr + w * v3.y;
        m = mn;

        qr = qn; vr = vn;
    }

    float inv = (cnt > 0) ? 1.f / z : 0.f;
    float* dst = out + (size_t)d * 256 + off;
    *reinterpret_cast<float4*>(dst)     = make_float4(a[0] * inv, a[1] * inv, a[2] * inv, a[3] * inv);
    *reinterpret_cast<float4*>(dst + 4) = make_float4(a[4] * inv, a[5] * inv, a[6] * inv, a[7] * inv);
}

// ---------------- launch ----------------
extern "C" void kernel_launch(void* const* d_in, const int* in_sizes, int n_in,
                              void* d_out, int out_size) {
    const float* x  = (const float*)d_in[0];
    const float* Wq = (const float*)d_in[1];
    const float* bq = (const float*)d_in[2];
    const float* Wk = (const float*)d_in[3];
    const float* bk = (const float*)d_in[4];
    const float* Wv = (const float*)d_in[5];
    const float* bv = (const float*)d_in[6];
    const int* src  = (const int*)d_in[7];
    const int* dst  = (const int*)d_in[8];
    float* out = (float*)d_out;

    cudaFuncSetAttribute(gemm_mma_kernel, cudaFuncAttributeMaxDynamicSharedMemorySize, SMEM_TOTAL);

    size_t nconv = (size_t)NM_PAD * 32;
    convertA_kernel<<<(unsigned)((nconv + 255) / 256), 256>>>(x);
    packB_kernel<<<(256 * NINNER + 255) / 256, 256>>>(Wq, bq, Wk, bk, Wv, bv);

    dim3 ggrid(NM_PAD / BM, NINNER / BN);  // 391 x 6
    gemm_mma_kernel<<<ggrid, 256, SMEM_TOTAL>>>();

    scatter_kernel<<<(NE + 255) / 256, 256>>>(src, dst);

    attn_kernel<<<(NN + 7) / 8, 256>>>(out);
}